// round 8
// baseline (speedup 1.0000x reference)
#include <cuda_runtime.h>
#include <cuda_fp16.h>
#include <mma.h>
#include <cstdint>
using namespace nvcuda;

// ---------------- problem constants ----------------
#define BB    16
#define TT    3000
#define CC    32
#define HH    32
#define WW    375
#define DSW   192
#define PP    32
#define DMODEL 512
#define HID   128
#define NF    128

#define ACOUSTIC_SIZE (BB * NF * 64 * DMODEL)     // 67,108,864
#define ALPHA_OFF     ACOUSTIC_SIZE
#define QTY_OFF       (ALPHA_OFF + BB * TT)

#define NROWS   (BB * NF * 32)     // 65536 GEMM rows per matrix
#define KS_SW   13                 // swin k-steps of 16
#define KS_PI   3                  // pitch k-steps
#define NTILES  4                  // DMODEL / 128

// ---------------- scratch (no allocs allowed) ----------------
__device__ int    g_fire_w[BB * NF];
__device__ float  g_qdiff[BB];
__device__ __align__(256) __half g_Asw[(size_t)KS_SW * NROWS * 16];   // 27.3MB
__device__ __align__(256) __half g_Api[(size_t)KS_PI * NROWS * 16];   // 6.3MB
__device__ __align__(256) __half g_Bsw[NTILES * KS_SW * 2048];
__device__ __align__(256) __half g_Bpi[NTILES * KS_PI * 2048];

// ---------------- helpers ----------------
__device__ __forceinline__ float warp_sum(float v) {
#pragma unroll
    for (int o = 16; o > 0; o >>= 1) v += __shfl_xor_sync(0xffffffffu, v, o);
    return v;
}
__device__ __forceinline__ void cp16s(unsigned saddr, const void* g) {
    asm volatile("cp.async.cg.shared.global [%0], [%1], 16;" :: "r"(saddr), "l"(g));
}
__device__ __forceinline__ void cp_commit() {
    asm volatile("cp.async.commit_group;" ::: "memory");
}
template <int N>
__device__ __forceinline__ void cp_wait() {
    asm volatile("cp.async.wait_group %0;" :: "n"(N) : "memory");
}

// ============================================================
// Kernel 1: alpha — 4 consecutive t per warp, float4 weight LDS
// ============================================================
__global__ __launch_bounds__(256) void alpha_kernel(
    const float* __restrict__ fs,
    const float* __restrict__ conv_w,
    const float* __restrict__ ln_w,  const float* __restrict__ ln_b,
    const float* __restrict__ dense_w, const float* __restrict__ dense_b,
    const float* __restrict__ proj_w,  const float* __restrict__ proj_b,
    float* __restrict__ alpha_out)
{
    __shared__ float4 s_dw4[CC * 32];
    __shared__ float4 s_db4[32], s_pw4[32];
    __shared__ float  s_cw[CC * 3], s_lnw[CC], s_lnb[CC];

    int tid = threadIdx.x;
    for (int i = tid; i < CC * HID; i += 256) {
        int cc = i >> 7, j = i & 127;
        int q = j >> 5, l = j & 31;
        ((float*)s_dw4)[cc * 128 + l * 4 + q] = dense_w[i];
    }
    if (tid < HID) {
        int q = tid >> 5, l = tid & 31;
        ((float*)s_db4)[l * 4 + q] = dense_b[tid];
        ((float*)s_pw4)[l * 4 + q] = proj_w[tid];
    }
    if (tid < CC * 3) s_cw[tid] = conv_w[tid];
    if (tid < CC) { s_lnw[tid] = ln_w[tid]; s_lnb[tid] = ln_b[tid]; }
    __syncthreads();

    int warp = tid >> 5, lane = tid & 31;
    int g = blockIdx.x * 8 + warp;
    int t0 = (g * 4) % TT;
    int b  = (g * 4) / TT;

    const float* base = fs + ((size_t)b * TT + t0) * CC + lane;
    float xv[6];
#pragma unroll
    for (int j = 0; j < 6; j++) {
        int t = t0 - 1 + j;
        xv[j] = (t >= 0 && t < TT) ? base[(j - 1) * CC] : 0.f;
    }

    float cw0 = s_cw[lane * 3], cw1 = s_cw[lane * 3 + 1], cw2 = s_cw[lane * 3 + 2];
    float lnw = s_lnw[lane], lnb = s_lnb[lane];

    float xn[4];
#pragma unroll
    for (int i = 0; i < 4; i++) {
        float x = fmaf(cw0, xv[i], fmaf(cw1, xv[i + 1], cw2 * xv[i + 2])) + xv[i + 1];
        float mu  = warp_sum(x) * (1.f / CC);
        float d   = x - mu;
        float var = warp_sum(d * d) * (1.f / CC);
        xn[i] = d * rsqrtf(var + 1e-5f) * lnw + lnb;
    }

    float4 db = s_db4[lane];
    float4 h[4] = {db, db, db, db};
#pragma unroll
    for (int cc = 0; cc < CC; cc++) {
        float4 w = s_dw4[cc * 32 + lane];
#pragma unroll
        for (int i = 0; i < 4; i++) {
            float v = __shfl_sync(0xffffffffu, xn[i], cc);
            h[i].x = fmaf(v, w.x, h[i].x);
            h[i].y = fmaf(v, w.y, h[i].y);
            h[i].z = fmaf(v, w.z, h[i].z);
            h[i].w = fmaf(v, w.w, h[i].w);
        }
    }

    float4 pw = s_pw4[lane];
    float ps[4];
#pragma unroll
    for (int i = 0; i < 4; i++) {
        float p = fmaxf(h[i].x, 0.f) * pw.x + fmaxf(h[i].y, 0.f) * pw.y
                + fmaxf(h[i].z, 0.f) * pw.z + fmaxf(h[i].w, 0.f) * pw.w;
        ps[i] = warp_sum(p);
    }

    if (lane < 4) {
        float psel = (lane == 0) ? ps[0] : (lane == 1) ? ps[1]
                   : (lane == 2) ? ps[2] : ps[3];
        float a  = psel + proj_b[0];
        float sp = fmaxf(a, 0.f) + log1pf(expf(-fabsf(a)));
        alpha_out[(size_t)b * TT + t0 + lane] = sp;
    }
}

// ============================================================
// Kernel 2: fires (warp-scan, 2 barriers)
// ============================================================
__global__ __launch_bounds__(1024) void fires_kernel(
    const float* __restrict__ alpha, const int* __restrict__ tlen)
{
    __shared__ int   s_wsum[32];
    __shared__ int   s_frame[NF];
    __shared__ float s_red[32];

    int b = blockIdx.x, tid = threadIdx.x;
    int lane = tid & 31, warp = tid >> 5;
    if (tid < NF) s_frame[tid] = TT - 1;

    const float* arow = alpha + (size_t)b * TT;
    int base = tid * 3;
    int pred[3] = {0, 0, 0};
    int mycnt = 0; float onset = 0.f;
#pragma unroll
    for (int i = 0; i < 3; i++) {
        int t = base + i;
        if (t < TT) {
            float a = arow[t];
            int pr = (a > 1.0f);
            pred[i] = pr; mycnt += pr;
            onset += 1.f / (1.f + expf(-(a - 1.0f) * 10.f));
        }
    }
    int scan = mycnt;
#pragma unroll
    for (int o = 1; o < 32; o <<= 1) {
        int v = __shfl_up_sync(0xffffffffu, scan, o);
        if (lane >= o) scan += v;
    }
    if (lane == 31) s_wsum[warp] = scan;
    float os = warp_sum(onset);
    if (lane == 0) s_red[warp] = os;
    __syncthreads();
    if (warp == 0) {
        int ws = s_wsum[lane];
#pragma unroll
        for (int o = 1; o < 32; o <<= 1) {
            int v = __shfl_up_sync(0xffffffffu, ws, o);
            if (lane >= o) ws += v;
        }
        s_wsum[lane] = ws;
        float v = warp_sum(s_red[lane]);
        if (lane == 0) g_qdiff[b] = fabsf(v - (float)tlen[b]);
    }
    __syncthreads();
    int c = scan - mycnt + (warp > 0 ? s_wsum[warp - 1] : 0);
#pragma unroll
    for (int i = 0; i < 3; i++) {
        if (pred[i]) {
            c += 1;
            if (c <= NF) s_frame[c - 1] = base + i;
        }
    }
    __syncthreads();
    if (tid < NF) g_fire_w[b * NF + tid] = s_frame[tid] >> 3;
}

__global__ void qty_kernel(float* __restrict__ out) {
    int tid = threadIdx.x;
    float v = (tid < BB) ? g_qdiff[tid] : 0.f;
    v = warp_sum(v);
    if (tid == 0) out[0] = v * (1.f / BB);
}

// ============================================================
// Packing kernels (fp16 RN, bias row folded, k-step blocked)
// ============================================================
__global__ __launch_bounds__(256) void pack_b_kernel(
    const float* __restrict__ sw_w, const float* __restrict__ sw_b,
    const float* __restrict__ pi_w, const float* __restrict__ pi_b)
{
    int idx = blockIdx.x * 256 + threadIdx.x;
    const int SWTOT = NTILES * KS_SW * 2048;
    if (idx < SWTOT) {
        int nt = idx / (KS_SW * 2048);
        int rem = idx % (KS_SW * 2048);
        int j = rem / 2048, e = rem % 2048;
        int kr = e >> 7, n = e & 127;
        int k = j * 16 + kr;
        float v = (k < DSW) ? sw_w[k * DMODEL + nt * 128 + n]
                : (k == DSW ? sw_b[nt * 128 + n] : 0.f);
        g_Bsw[idx] = __float2half_rn(v);
    } else {
        int x = idx - SWTOT;
        if (x >= NTILES * KS_PI * 2048) return;
        int nt = x / (KS_PI * 2048);
        int rem = x % (KS_PI * 2048);
        int j = rem / 2048, e = rem % 2048;
        int kr = e >> 7, n = e & 127;
        int k = j * 16 + kr;
        float v = (k < 32) ? pi_w[k * DMODEL + nt * 128 + n]
                : (k == 32 ? pi_b[nt * 128 + n] : 0.f);
        g_Bpi[x] = __float2half_rn(v);
    }
}

__global__ __launch_bounds__(256) void pack_a_pitch(const float* __restrict__ pitch)
{
    int warp = threadIdx.x >> 5, lane = threadIdx.x & 31;
    int r = blockIdx.x * 8 + warp;
    float v = pitch[(size_t)r * 32 + lane];
    g_Api[((size_t)(lane >> 4) * NROWS + r) * 16 + (lane & 15)] = __float2half_rn(v);
    if (lane < 16)
        g_Api[((size_t)2 * NROWS + r) * 16 + lane] =
            __float2half_rn(lane == 0 ? 1.f : 0.f);
}

__global__ __launch_bounds__(256) void pack_a_swin(const float* __restrict__ swin)
{
    int warp = threadIdx.x >> 5, lane = threadIdx.x & 31;
    int r = blockIdx.x * 8 + warp;
    int b = r >> 12, n = (r >> 5) & 127, h = r & 31;
    int w = g_fire_w[b * NF + n];
    const float* src = swin + (size_t)((b * HH + h) * WW + w) * DSW;
#pragma unroll
    for (int j = 0; j < 6; j++) {
        int k = j * 32 + lane;
        float v = src[k];
        g_Asw[((size_t)(k >> 4) * NROWS + r) * 16 + (k & 15)] = __float2half_rn(v);
    }
    if (lane < 16)
        g_Asw[((size_t)12 * NROWS + r) * 16 + lane] =
            __float2half_rn(lane == 0 ? 1.f : 0.f);
}

// ============================================================
// fp16 wmma GEMM: 128x128 tile, k-step(16) multistage cp.async
// dynamic smem, fully unrolled k loop
// ============================================================
#define ASTR 24     // halves (48B rows)
#define BSTR 136    // halves (272B rows)
#define A_ST_H (128 * ASTR)       // halves per A stage
#define B_ST_H (16 * BSTR)        // halves per B stage

template<int KSTEPS, int NSTAGE, int SLOTBASE>
__global__ __launch_bounds__(256, 2) void gemm_fp16(float* __restrict__ out)
{
    extern __shared__ __half smem_h[];
    __half* As = smem_h;                       // NSTAGE * A_ST_H
    __half* Bs = smem_h + NSTAGE * A_ST_H;     // NSTAGE * B_ST_H

    const __half* __restrict__ Apk = (SLOTBASE == 0) ? g_Api : g_Asw;
    const __half* __restrict__ Bpk = (SLOTBASE == 0) ? g_Bpi : g_Bsw;

    int tid = threadIdx.x;
    int m0 = blockIdx.y * 128;
    int nt = blockIdx.x;
    int n0 = nt * 128;

    unsigned sA = (unsigned)__cvta_generic_to_shared(As);
    unsigned sB = (unsigned)__cvta_generic_to_shared(Bs);
    const unsigned ASTAGE = A_ST_H * sizeof(__half);
    const unsigned BSTAGE = B_ST_H * sizeof(__half);

    int arow = tid >> 1, aseg = tid & 1;
    int brow = tid >> 4, bseg = tid & 15;

    auto load_stage = [&](int j, int st) {
        const __half* asrc = Apk + ((size_t)j * NROWS + m0) * 16;
        const __half* bsrc = Bpk + (size_t)(nt * KSTEPS + j) * 2048;
        cp16s(sA + st * ASTAGE + arow * (ASTR * 2) + aseg * 16,
              asrc + arow * 16 + aseg * 8);
        cp16s(sB + st * BSTAGE + brow * (BSTR * 2) + bseg * 16,
              bsrc + brow * 128 + bseg * 8);
    };

    int warp = tid >> 5;
    int wm = warp & 1, wn = warp >> 1;

    wmma::fragment<wmma::accumulator, 16, 16, 16, float> acc[4][2];
#pragma unroll
    for (int mi = 0; mi < 4; mi++)
#pragma unroll
        for (int ni = 0; ni < 2; ni++) wmma::fill_fragment(acc[mi][ni], 0.f);

#pragma unroll
    for (int p = 0; p < NSTAGE - 1; p++) {
        if (p < KSTEPS) load_stage(p, p);
        cp_commit();
    }

#pragma unroll
    for (int j = 0; j < KSTEPS; j++) {
        const int st = j % NSTAGE;
        cp_wait<NSTAGE - 2>();
        __syncthreads();

        const int jn = j + NSTAGE - 1;
        if (jn < KSTEPS) load_stage(jn, jn % NSTAGE);
        cp_commit();

        const __half* Ac = As + st * A_ST_H;
        const __half* Bc = Bs + st * B_ST_H;

        wmma::fragment<wmma::matrix_a, 16, 16, 16, __half, wmma::row_major> af[4];
        wmma::fragment<wmma::matrix_b, 16, 16, 16, __half, wmma::row_major> bf[2];
#pragma unroll
        for (int mi = 0; mi < 4; mi++)
            wmma::load_matrix_sync(af[mi], Ac + (wm * 64 + mi * 16) * ASTR, ASTR);
#pragma unroll
        for (int ni = 0; ni < 2; ni++)
            wmma::load_matrix_sync(bf[ni], Bc + wn * 32 + ni * 16, BSTR);
#pragma unroll
        for (int mi = 0; mi < 4; mi++)
#pragma unroll
            for (int ni = 0; ni < 2; ni++)
                wmma::mma_sync(acc[mi][ni], af[mi], bf[ni], acc[mi][ni]);
    }

#pragma unroll
    for (int mi = 0; mi < 4; mi++)
#pragma unroll
        for (int ni = 0; ni < 2; ni++) {
            int r0 = m0 + wm * 64 + mi * 16;
            size_t off = (size_t)(r0 >> 5) * 32768
                       + (size_t)((r0 & 31) + SLOTBASE) * 512
                       + n0 + wn * 32 + ni * 16;
            wmma::store_matrix_sync(out + off, acc[mi][ni], 512, wmma::mem_row_major);
        }
}

#define SMEM_SW ((6 * A_ST_H + 6 * B_ST_H) * (int)sizeof(__half))   // 62976
#define SMEM_PI ((3 * A_ST_H + 3 * B_ST_H) * (int)sizeof(__half))   // 31488

// ============================================================
extern "C" void kernel_launch(void* const* d_in, const int* in_sizes, int n_in,
                              void* d_out, int out_size)
{
    const float* fs      = (const float*)d_in[0];
    const float* swin    = (const float*)d_in[1];
    const float* pitch   = (const float*)d_in[2];
    const int*   tlen    = (const int*)  d_in[3];
    const float* conv_w  = (const float*)d_in[4];
    const float* ln_w    = (const float*)d_in[5];
    const float* ln_b    = (const float*)d_in[6];
    const float* dense_w = (const float*)d_in[7];
    const float* dense_b = (const float*)d_in[8];
    const float* proj_w  = (const float*)d_in[9];
    const float* proj_b  = (const float*)d_in[10];
    const float* pitch_w = (const float*)d_in[11];
    const float* pitch_b = (const float*)d_in[12];
    const float* swin_w  = (const float*)d_in[13];
    const float* swin_b  = (const float*)d_in[14];
    float* out = (float*)d_out;

    static cudaStream_t s1 = nullptr;
    static cudaEvent_t ev_root = nullptr, ev_join = nullptr;
    static bool init_tried = false;
    if (!init_tried) {
        init_tried = true;
        cudaFuncSetAttribute(gemm_fp16<KS_SW, 6, 32>,
            cudaFuncAttributeMaxDynamicSharedMemorySize, SMEM_SW);
        cudaFuncSetAttribute(gemm_fp16<KS_PI, 3, 0>,
            cudaFuncAttributeMaxDynamicSharedMemorySize, SMEM_PI);
        if (cudaStreamCreateWithFlags(&s1, cudaStreamNonBlocking) != cudaSuccess) s1 = nullptr;
        if (s1) {
            if (cudaEventCreateWithFlags(&ev_root, cudaEventDisableTiming) != cudaSuccess ||
                cudaEventCreateWithFlags(&ev_join, cudaEventDisableTiming) != cudaSuccess) {
                s1 = nullptr;
            }
        }
    }

    dim3 grid(NTILES, NROWS / 128);   // (4, 512)

    if (s1) {
        cudaEventRecord(ev_root, 0);
        cudaStreamWaitEvent(s1, ev_root, 0);

        // independent pitch chain on s1
        pack_b_kernel<<<(NTILES * (KS_SW + KS_PI) * 2048 + 255) / 256, 256, 0, s1>>>(
            swin_w, swin_b, pitch_w, pitch_b);
        pack_a_pitch<<<NROWS / 8, 256, 0, s1>>>(pitch);
        gemm_fp16<KS_PI, 3, 0><<<grid, 256, SMEM_PI, s1>>>(out);

        // main chain on default stream
        alpha_kernel<<<1500, 256>>>(fs, conv_w, ln_w, ln_b,
                                    dense_w, dense_b, proj_w, proj_b,
                                    out + ALPHA_OFF);
        fires_kernel<<<BB, 1024>>>(out + ALPHA_OFF, tlen);
        pack_a_swin<<<NROWS / 8, 256>>>(swin);

        // qty on s1 (depends only on fires' g_qdiff): fires is on stream0,
        // so fork an event after fires
        cudaEventRecord(ev_join, 0);                 // after fires+pack enqueued
        cudaStreamWaitEvent(s1, ev_join, 0);
        qty_kernel<<<1, 32, 0, s1>>>(out + QTY_OFF);

        gemm_fp16<KS_SW, 6, 32><<<grid, 256, SMEM_SW>>>(out);

        // join s1 back into stream0
        cudaEventRecord(ev_root, s1);
        cudaStreamWaitEvent(0, ev_root, 0);
    } else {
        alpha_kernel<<<1500, 256>>>(fs, conv_w, ln_w, ln_b,
                                    dense_w, dense_b, proj_w, proj_b,
                                    out + ALPHA_OFF);
        fires_kernel<<<BB, 1024>>>(out + ALPHA_OFF, tlen);
        qty_kernel<<<1, 32>>>(out + QTY_OFF);
        pack_b_kernel<<<(NTILES * (KS_SW + KS_PI) * 2048 + 255) / 256, 256>>>(
            swin_w, swin_b, pitch_w, pitch_b);
        pack_a_pitch<<<NROWS / 8, 256>>>(pitch);
        pack_a_swin<<<NROWS / 8, 256>>>(swin);
        gemm_fp16<KS_SW, 6, 32><<<grid, 256, SMEM_SW>>>(out);
        gemm_fp16<KS_PI, 3, 0><<<grid, 256, SMEM_PI>>>(out);
    }
}

// round 9
// speedup vs baseline: 1.2528x; 1.2528x over previous
#include <cuda_runtime.h>
#include <cuda_fp16.h>
#include <mma.h>
#include <cstdint>
using namespace nvcuda;

// ---------------- problem constants ----------------
#define BB    16
#define TT    3000
#define CC    32
#define HH    32
#define WW    375
#define DSW   192
#define PP    32
#define DMODEL 512
#define HID   128
#define NF    128

#define ACOUSTIC_SIZE (BB * NF * 64 * DMODEL)
#define ALPHA_OFF     ACOUSTIC_SIZE
#define QTY_OFF       (ALPHA_OFF + BB * TT)

#define NROWS   (BB * NF * 32)     // 65536 GEMM rows
#define KS_SW   13                 // swin k-steps of 16 (12 data + 1 bias)
#define KS_PI   3                  // pitch k-steps
#define NTILES  4                  // DMODEL / 128

// ---------------- scratch ----------------
__device__ int    g_fire_w[BB * NF];
__device__ float  g_qdiff[BB];
__device__ __align__(256) __half g_Api[(size_t)KS_PI * NROWS * 16];
__device__ __align__(256) __half g_Bsw[NTILES * KS_SW * 2048];
__device__ __align__(256) __half g_Bpi[NTILES * KS_PI * 2048];

// ---------------- helpers ----------------
__device__ __forceinline__ float warp_sum(float v) {
#pragma unroll
    for (int o = 16; o > 0; o >>= 1) v += __shfl_xor_sync(0xffffffffu, v, o);
    return v;
}
__device__ __forceinline__ void cp16s(unsigned saddr, const void* g) {
    asm volatile("cp.async.cg.shared.global [%0], [%1], 16;" :: "r"(saddr), "l"(g));
}
__device__ __forceinline__ void cp_commit() {
    asm volatile("cp.async.commit_group;" ::: "memory");
}
template <int N>
__device__ __forceinline__ void cp_wait() {
    asm volatile("cp.async.wait_group %0;" :: "n"(N) : "memory");
}

// ============================================================
// Kernel 1: alpha — 4 consecutive t per warp, float4 weight LDS
// ============================================================
__global__ __launch_bounds__(256) void alpha_kernel(
    const float* __restrict__ fs,
    const float* __restrict__ conv_w,
    const float* __restrict__ ln_w,  const float* __restrict__ ln_b,
    const float* __restrict__ dense_w, const float* __restrict__ dense_b,
    const float* __restrict__ proj_w,  const float* __restrict__ proj_b,
    float* __restrict__ alpha_out)
{
    __shared__ float4 s_dw4[CC * 32];
    __shared__ float4 s_db4[32], s_pw4[32];
    __shared__ float  s_cw[CC * 3], s_lnw[CC], s_lnb[CC];

    int tid = threadIdx.x;
    for (int i = tid; i < CC * HID; i += 256) {
        int cc = i >> 7, j = i & 127;
        int q = j >> 5, l = j & 31;
        ((float*)s_dw4)[cc * 128 + l * 4 + q] = dense_w[i];
    }
    if (tid < HID) {
        int q = tid >> 5, l = tid & 31;
        ((float*)s_db4)[l * 4 + q] = dense_b[tid];
        ((float*)s_pw4)[l * 4 + q] = proj_w[tid];
    }
    if (tid < CC * 3) s_cw[tid] = conv_w[tid];
    if (tid < CC) { s_lnw[tid] = ln_w[tid]; s_lnb[tid] = ln_b[tid]; }
    __syncthreads();

    int warp = tid >> 5, lane = tid & 31;
    int g = blockIdx.x * 8 + warp;
    int t0 = (g * 4) % TT;
    int b  = (g * 4) / TT;

    const float* base = fs + ((size_t)b * TT + t0) * CC + lane;
    float xv[6];
#pragma unroll
    for (int j = 0; j < 6; j++) {
        int t = t0 - 1 + j;
        xv[j] = (t >= 0 && t < TT) ? base[(j - 1) * CC] : 0.f;
    }

    float cw0 = s_cw[lane * 3], cw1 = s_cw[lane * 3 + 1], cw2 = s_cw[lane * 3 + 2];
    float lnw = s_lnw[lane], lnb = s_lnb[lane];

    float xn[4];
#pragma unroll
    for (int i = 0; i < 4; i++) {
        float x = fmaf(cw0, xv[i], fmaf(cw1, xv[i + 1], cw2 * xv[i + 2])) + xv[i + 1];
        float mu  = warp_sum(x) * (1.f / CC);
        float d   = x - mu;
        float var = warp_sum(d * d) * (1.f / CC);
        xn[i] = d * rsqrtf(var + 1e-5f) * lnw + lnb;
    }

    float4 db = s_db4[lane];
    float4 h[4] = {db, db, db, db};
#pragma unroll
    for (int cc = 0; cc < CC; cc++) {
        float4 w = s_dw4[cc * 32 + lane];
#pragma unroll
        for (int i = 0; i < 4; i++) {
            float v = __shfl_sync(0xffffffffu, xn[i], cc);
            h[i].x = fmaf(v, w.x, h[i].x);
            h[i].y = fmaf(v, w.y, h[i].y);
            h[i].z = fmaf(v, w.z, h[i].z);
            h[i].w = fmaf(v, w.w, h[i].w);
        }
    }

    float4 pw = s_pw4[lane];
    float ps[4];
#pragma unroll
    for (int i = 0; i < 4; i++) {
        float p = fmaxf(h[i].x, 0.f) * pw.x + fmaxf(h[i].y, 0.f) * pw.y
                + fmaxf(h[i].z, 0.f) * pw.z + fmaxf(h[i].w, 0.f) * pw.w;
        ps[i] = warp_sum(p);
    }

    if (lane < 4) {
        float psel = (lane == 0) ? ps[0] : (lane == 1) ? ps[1]
                   : (lane == 2) ? ps[2] : ps[3];
        float a  = psel + proj_b[0];
        float sp = fmaxf(a, 0.f) + log1pf(expf(-fabsf(a)));
        alpha_out[(size_t)b * TT + t0 + lane] = sp;
    }
}

// ============================================================
// Kernel 2: fires (warp-scan, 2 barriers)
// ============================================================
__global__ __launch_bounds__(1024) void fires_kernel(
    const float* __restrict__ alpha, const int* __restrict__ tlen)
{
    __shared__ int   s_wsum[32];
    __shared__ int   s_frame[NF];
    __shared__ float s_red[32];

    int b = blockIdx.x, tid = threadIdx.x;
    int lane = tid & 31, warp = tid >> 5;
    if (tid < NF) s_frame[tid] = TT - 1;

    const float* arow = alpha + (size_t)b * TT;
    int base = tid * 3;
    int pred[3] = {0, 0, 0};
    int mycnt = 0; float onset = 0.f;
#pragma unroll
    for (int i = 0; i < 3; i++) {
        int t = base + i;
        if (t < TT) {
            float a = arow[t];
            int pr = (a > 1.0f);
            pred[i] = pr; mycnt += pr;
            onset += 1.f / (1.f + expf(-(a - 1.0f) * 10.f));
        }
    }
    int scan = mycnt;
#pragma unroll
    for (int o = 1; o < 32; o <<= 1) {
        int v = __shfl_up_sync(0xffffffffu, scan, o);
        if (lane >= o) scan += v;
    }
    if (lane == 31) s_wsum[warp] = scan;
    float os = warp_sum(onset);
    if (lane == 0) s_red[warp] = os;
    __syncthreads();
    if (warp == 0) {
        int ws = s_wsum[lane];
#pragma unroll
        for (int o = 1; o < 32; o <<= 1) {
            int v = __shfl_up_sync(0xffffffffu, ws, o);
            if (lane >= o) ws += v;
        }
        s_wsum[lane] = ws;
        float v = warp_sum(s_red[lane]);
        if (lane == 0) g_qdiff[b] = fabsf(v - (float)tlen[b]);
    }
    __syncthreads();
    int c = scan - mycnt + (warp > 0 ? s_wsum[warp - 1] : 0);
#pragma unroll
    for (int i = 0; i < 3; i++) {
        if (pred[i]) {
            c += 1;
            if (c <= NF) s_frame[c - 1] = base + i;
        }
    }
    __syncthreads();
    if (tid < NF) g_fire_w[b * NF + tid] = s_frame[tid] >> 3;
}

__global__ void qty_kernel(float* __restrict__ out) {
    int tid = threadIdx.x;
    float v = (tid < BB) ? g_qdiff[tid] : 0.f;
    v = warp_sum(v);
    if (tid == 0) out[0] = v * (1.f / BB);
}

// ============================================================
// Packing kernels (pitch + B only; swin A gather fused into GEMM)
// ============================================================
__global__ __launch_bounds__(256) void pack_b_kernel(
    const float* __restrict__ sw_w, const float* __restrict__ sw_b,
    const float* __restrict__ pi_w, const float* __restrict__ pi_b)
{
    int idx = blockIdx.x * 256 + threadIdx.x;
    const int SWTOT = NTILES * KS_SW * 2048;
    if (idx < SWTOT) {
        int nt = idx / (KS_SW * 2048);
        int rem = idx % (KS_SW * 2048);
        int j = rem / 2048, e = rem % 2048;
        int kr = e >> 7, n = e & 127;
        int k = j * 16 + kr;
        float v = (k < DSW) ? sw_w[k * DMODEL + nt * 128 + n]
                : (k == DSW ? sw_b[nt * 128 + n] : 0.f);
        g_Bsw[idx] = __float2half_rn(v);
    } else {
        int x = idx - SWTOT;
        if (x >= NTILES * KS_PI * 2048) return;
        int nt = x / (KS_PI * 2048);
        int rem = x % (KS_PI * 2048);
        int j = rem / 2048, e = rem % 2048;
        int kr = e >> 7, n = e & 127;
        int k = j * 16 + kr;
        float v = (k < 32) ? pi_w[k * DMODEL + nt * 128 + n]
                : (k == 32 ? pi_b[nt * 128 + n] : 0.f);
        g_Bpi[x] = __float2half_rn(v);
    }
}

__global__ __launch_bounds__(256) void pack_a_pitch(const float* __restrict__ pitch)
{
    int warp = threadIdx.x >> 5, lane = threadIdx.x & 31;
    int r = blockIdx.x * 8 + warp;
    float v = pitch[(size_t)r * 32 + lane];
    g_Api[((size_t)(lane >> 4) * NROWS + r) * 16 + (lane & 15)] = __float2half_rn(v);
    if (lane < 16)
        g_Api[((size_t)2 * NROWS + r) * 16 + lane] =
            __float2half_rn(lane == 0 ? 1.f : 0.f);
}

// ============================================================
// pitch GEMM: R7-style static-smem 3-stage fp16 wmma
// ============================================================
#define ASTR 24
#define BSTR 136

__global__ __launch_bounds__(256, 2) void pitch_gemm(float* __restrict__ out)
{
    const int NSTAGE = 3, KSTEPS = KS_PI;
    __shared__ __align__(16) __half As[NSTAGE][128 * ASTR];
    __shared__ __align__(16) __half Bs[NSTAGE][16 * BSTR];

    int tid = threadIdx.x;
    int m0 = blockIdx.y * 128;
    int nt = blockIdx.x;
    int n0 = nt * 128;

    unsigned sA = (unsigned)__cvta_generic_to_shared(&As[0][0]);
    unsigned sB = (unsigned)__cvta_generic_to_shared(&Bs[0][0]);
    const unsigned ASTAGE = 128 * ASTR * sizeof(__half);
    const unsigned BSTAGE = 16 * BSTR * sizeof(__half);

    int arow = tid >> 1, aseg = tid & 1;
    int brow = tid >> 4, bseg = tid & 15;

    auto load_stage = [&](int j, int st) {
        const __half* asrc = g_Api + ((size_t)j * NROWS + m0) * 16;
        const __half* bsrc = g_Bpi + (size_t)(nt * KSTEPS + j) * 2048;
        cp16s(sA + st * ASTAGE + arow * (ASTR * 2) + aseg * 16,
              asrc + arow * 16 + aseg * 8);
        cp16s(sB + st * BSTAGE + brow * (BSTR * 2) + bseg * 16,
              bsrc + brow * 128 + bseg * 8);
    };

    int warp = tid >> 5;
    int wm = warp & 1, wn = warp >> 1;

    wmma::fragment<wmma::accumulator, 16, 16, 16, float> acc[4][2];
#pragma unroll
    for (int mi = 0; mi < 4; mi++)
#pragma unroll
        for (int ni = 0; ni < 2; ni++) wmma::fill_fragment(acc[mi][ni], 0.f);

#pragma unroll
    for (int p = 0; p < NSTAGE - 1; p++) { load_stage(p, p); cp_commit(); }

    for (int j = 0; j < KSTEPS; j++) {
        int st = j % NSTAGE;
        cp_wait<1>();
        __syncthreads();

        int jn = j + NSTAGE - 1;
        if (jn < KSTEPS) load_stage(jn, jn % NSTAGE);
        cp_commit();

        const __half* Ac = &As[0][0] + st * 128 * ASTR;
        const __half* Bc = &Bs[0][0] + st * 16 * BSTR;

        wmma::fragment<wmma::matrix_a, 16, 16, 16, __half, wmma::row_major> af[4];
        wmma::fragment<wmma::matrix_b, 16, 16, 16, __half, wmma::row_major> bf[2];
#pragma unroll
        for (int mi = 0; mi < 4; mi++)
            wmma::load_matrix_sync(af[mi], Ac + (wm * 64 + mi * 16) * ASTR, ASTR);
#pragma unroll
        for (int ni = 0; ni < 2; ni++)
            wmma::load_matrix_sync(bf[ni], Bc + wn * 32 + ni * 16, BSTR);
#pragma unroll
        for (int mi = 0; mi < 4; mi++)
#pragma unroll
            for (int ni = 0; ni < 2; ni++)
                wmma::mma_sync(acc[mi][ni], af[mi], bf[ni], acc[mi][ni]);
    }

#pragma unroll
    for (int mi = 0; mi < 4; mi++)
#pragma unroll
        for (int ni = 0; ni < 2; ni++) {
            int r0 = m0 + wm * 64 + mi * 16;
            size_t off = (size_t)(r0 >> 5) * 32768
                       + (size_t)(r0 & 31) * 512
                       + n0 + wn * 32 + ni * 16;
            wmma::store_matrix_sync(out + off, acc[mi][ni], 512, wmma::mem_row_major);
        }
}

// ============================================================
// swin GEMM, FUSED gather+convert:
//  - s_ptr[128] row pointers from g_fire_w
//  - cp.async fp32 A (k-steps 0..11), bias step 12 synthesized
//  - per-stage fp32->fp16 convert into padded MMA tile
//  - 4-stage ring, same MMA schedule as R7
// dyn smem: A32 4*8192 | A16 4*6144 | B16 4*4352  = 74752 B
// ============================================================
#define SW_NST   4
#define A32_ST   8192u                 // bytes per fp32 A stage
#define A16_STH  (128 * ASTR)          // halves per fp16 A stage (3072)
#define B16_STH  (16 * BSTR)           // halves per B stage (2176)
#define SW_SMEM  (SW_NST * A32_ST + SW_NST * A16_STH * 2 + SW_NST * B16_STH * 2)

__global__ __launch_bounds__(256, 2) void swin_gemm_fused(
    const float* __restrict__ swin, float* __restrict__ out)
{
    extern __shared__ char sm[];
    float*  A32 = (float*)sm;
    __half* A16 = (__half*)(sm + SW_NST * A32_ST);
    __half* B16 = (__half*)(sm + SW_NST * A32_ST + SW_NST * A16_STH * 2);
    __shared__ const float* s_ptr[128];

    int tid = threadIdx.x;
    int m0 = blockIdx.y * 128;
    int nt = blockIdx.x;
    int n0 = nt * 128;

    if (tid < 128) {
        int r = m0 + tid;
        int b = r >> 12, n = (r >> 5) & 127, h = r & 31;
        int w = g_fire_w[b * NF + n];
        s_ptr[tid] = swin + (size_t)((b * HH + h) * WW + w) * DSW;
    }
    __syncthreads();

    unsigned sA32 = (unsigned)__cvta_generic_to_shared(A32);
    unsigned sB   = (unsigned)__cvta_generic_to_shared(B16);

    int arow = tid >> 1, aseg = tid & 1;   // A: 128 rows x 2 segs x 32B(fp32)
    int brow = tid >> 4, bseg = tid & 15;  // B: 16 rows x 16 x 16B

    auto load_stage = [&](int j, int st) {
        if (j < 12) {
            const float* src = s_ptr[arow] + j * 16 + aseg * 8;
            unsigned d = sA32 + st * A32_ST + arow * 64 + aseg * 32;
            cp16s(d, src);
            cp16s(d + 16, src + 4);
        }
        const __half* bsrc = g_Bsw + (size_t)(nt * KS_SW + j) * 2048;
        cp16s(sB + st * (B16_STH * 2) + brow * (BSTR * 2) + bseg * 16,
              bsrc + brow * 128 + bseg * 8);
    };

    int warp = tid >> 5;
    int wm = warp & 1, wn = warp >> 1;

    wmma::fragment<wmma::accumulator, 16, 16, 16, float> acc[4][2];
#pragma unroll
    for (int mi = 0; mi < 4; mi++)
#pragma unroll
        for (int ni = 0; ni < 2; ni++) wmma::fill_fragment(acc[mi][ni], 0.f);

#pragma unroll
    for (int p = 0; p < SW_NST - 1; p++) { load_stage(p, p); cp_commit(); }

    // per-thread convert lane: 8 floats at row=tid/2, col8=(tid&1)*8
    int crow = tid >> 1, ccol = (tid & 1) * 8;

    for (int j = 0; j < KS_SW; j++) {
        int st = j % SW_NST;
        cp_wait<SW_NST - 2>();
        __syncthreads();

        int jn = j + SW_NST - 1;
        if (jn < KS_SW) load_stage(jn, jn % SW_NST);
        cp_commit();

        // convert A stage st: fp32 -> fp16 (or synthesize bias step)
        __half* a16d = A16 + st * A16_STH + crow * ASTR + ccol;
        if (j < 12) {
            const float4* a32s = (const float4*)(A32 + st * 2048 + tid * 8);
            float4 v0 = a32s[0], v1 = a32s[1];
            __half2 h0 = __float22half2_rn(make_float2(v0.x, v0.y));
            __half2 h1 = __float22half2_rn(make_float2(v0.z, v0.w));
            __half2 h2 = __float22half2_rn(make_float2(v1.x, v1.y));
            __half2 h3 = __float22half2_rn(make_float2(v1.z, v1.w));
            ((__half2*)a16d)[0] = h0; ((__half2*)a16d)[1] = h1;
            ((__half2*)a16d)[2] = h2; ((__half2*)a16d)[3] = h3;
        } else {
            __half2 one0 = __halves2half2(__float2half_rn(ccol == 0 ? 1.f : 0.f),
                                          __float2half_rn(0.f));
            __half2 zz = __halves2half2(__float2half_rn(0.f), __float2half_rn(0.f));
            ((__half2*)a16d)[0] = one0; ((__half2*)a16d)[1] = zz;
            ((__half2*)a16d)[2] = zz;   ((__half2*)a16d)[3] = zz;
        }
        __syncthreads();

        const __half* Ac = A16 + st * A16_STH;
        const __half* Bc = B16 + st * B16_STH;

        wmma::fragment<wmma::matrix_a, 16, 16, 16, __half, wmma::row_major> af[4];
        wmma::fragment<wmma::matrix_b, 16, 16, 16, __half, wmma::row_major> bf[2];
#pragma unroll
        for (int mi = 0; mi < 4; mi++)
            wmma::load_matrix_sync(af[mi], Ac + (wm * 64 + mi * 16) * ASTR, ASTR);
#pragma unroll
        for (int ni = 0; ni < 2; ni++)
            wmma::load_matrix_sync(bf[ni], Bc + wn * 32 + ni * 16, BSTR);
#pragma unroll
        for (int mi = 0; mi < 4; mi++)
#pragma unroll
            for (int ni = 0; ni < 2; ni++)
                wmma::mma_sync(acc[mi][ni], af[mi], bf[ni], acc[mi][ni]);
    }

#pragma unroll
    for (int mi = 0; mi < 4; mi++)
#pragma unroll
        for (int ni = 0; ni < 2; ni++) {
            int r0 = m0 + wm * 64 + mi * 16;
            size_t off = (size_t)(r0 >> 5) * 32768
                       + (size_t)((r0 & 31) + 32) * 512
                       + n0 + wn * 32 + ni * 16;
            wmma::store_matrix_sync(out + off, acc[mi][ni], 512, wmma::mem_row_major);
        }
}

// ============================================================
extern "C" void kernel_launch(void* const* d_in, const int* in_sizes, int n_in,
                              void* d_out, int out_size)
{
    const float* fs      = (const float*)d_in[0];
    const float* swin    = (const float*)d_in[1];
    const float* pitch   = (const float*)d_in[2];
    const int*   tlen    = (const int*)  d_in[3];
    const float* conv_w  = (const float*)d_in[4];
    const float* ln_w    = (const float*)d_in[5];
    const float* ln_b    = (const float*)d_in[6];
    const float* dense_w = (const float*)d_in[7];
    const float* dense_b = (const float*)d_in[8];
    const float* proj_w  = (const float*)d_in[9];
    const float* proj_b  = (const float*)d_in[10];
    const float* pitch_w = (const float*)d_in[11];
    const float* pitch_b = (const float*)d_in[12];
    const float* swin_w  = (const float*)d_in[13];
    const float* swin_b  = (const float*)d_in[14];
    float* out = (float*)d_out;

    static cudaStream_t s1 = nullptr;
    static cudaEvent_t ev_root = nullptr, ev_b = nullptr, ev_join = nullptr;
    static bool init_tried = false;
    if (!init_tried) {
        init_tried = true;
        cudaFuncSetAttribute(swin_gemm_fused,
            cudaFuncAttributeMaxDynamicSharedMemorySize, SW_SMEM);
        if (cudaStreamCreateWithFlags(&s1, cudaStreamNonBlocking) != cudaSuccess) s1 = nullptr;
        if (s1) {
            if (cudaEventCreateWithFlags(&ev_root, cudaEventDisableTiming) != cudaSuccess ||
                cudaEventCreateWithFlags(&ev_b,    cudaEventDisableTiming) != cudaSuccess ||
                cudaEventCreateWithFlags(&ev_join, cudaEventDisableTiming) != cudaSuccess) {
                s1 = nullptr;
            }
        }
    }

    dim3 grid(NTILES, NROWS / 128);   // (4, 512)

    if (s1) {
        cudaEventRecord(ev_root, 0);
        cudaStreamWaitEvent(s1, ev_root, 0);

        // s1: independent pitch chain (+ B pack for both GEMMs)
        pack_b_kernel<<<(NTILES * (KS_SW + KS_PI) * 2048 + 255) / 256, 256, 0, s1>>>(
            swin_w, swin_b, pitch_w, pitch_b);
        cudaEventRecord(ev_b, s1);
        pack_a_pitch<<<NROWS / 8, 256, 0, s1>>>(pitch);
        pitch_gemm<<<grid, 256, 0, s1>>>(out);

        // s0: alpha -> fires -> qty -> swin fused GEMM
        alpha_kernel<<<1500, 256>>>(fs, conv_w, ln_w, ln_b,
                                    dense_w, dense_b, proj_w, proj_b,
                                    out + ALPHA_OFF);
        fires_kernel<<<BB, 1024>>>(out + ALPHA_OFF, tlen);
        qty_kernel<<<1, 32>>>(out + QTY_OFF);
        cudaStreamWaitEvent(0, ev_b, 0);   // g_Bsw ready
        swin_gemm_fused<<<grid, 256, SW_SMEM>>>(swin, out);

        cudaEventRecord(ev_join, s1);
        cudaStreamWaitEvent(0, ev_join, 0);
    } else {
        alpha_kernel<<<1500, 256>>>(fs, conv_w, ln_w, ln_b,
                                    dense_w, dense_b, proj_w, proj_b,
                                    out + ALPHA_OFF);
        fires_kernel<<<BB, 1024>>>(out + ALPHA_OFF, tlen);
        qty_kernel<<<1, 32>>>(out + QTY_OFF);
        pack_b_kernel<<<(NTILES * (KS_SW + KS_PI) * 2048 + 255) / 256, 256>>>(
            swin_w, swin_b, pitch_w, pitch_b);
        pack_a_pitch<<<NROWS / 8, 256>>>(pitch);
        pitch_gemm<<<grid, 256>>>(out);
        swin_gemm_fused<<<grid, 256, SW_SMEM>>>(swin, out);
    }
}

// round 10
// speedup vs baseline: 1.4763x; 1.1785x over previous
#include <cuda_runtime.h>
#include <cuda_fp16.h>
#include <mma.h>
#include <cstdint>
using namespace nvcuda;

// ---------------- problem constants ----------------
#define BB    16
#define TT    3000
#define CC    32
#define HH    32
#define WW    375
#define DSW   192
#define PP    32
#define DMODEL 512
#define HID   128
#define NF    128

#define ACOUSTIC_SIZE (BB * NF * 64 * DMODEL)
#define ALPHA_OFF     ACOUSTIC_SIZE
#define QTY_OFF       (ALPHA_OFF + BB * TT)

#define NROWS   (BB * NF * 32)     // 65536 GEMM rows
#define KS_SW   13                 // swin k-steps of 16
#define KS_PI   3                  // pitch k-steps
#define NTILES  4                  // DMODEL / 128

// ---------------- scratch ----------------
__device__ int    g_fire_w[BB * NF];
__device__ float  g_qdiff[BB];
__device__ __align__(256) __half g_Asw[(size_t)KS_SW * NROWS * 16];
__device__ __align__(256) __half g_Api[(size_t)KS_PI * NROWS * 16];
__device__ __align__(256) __half g_Bsw[NTILES * KS_SW * 2048];
__device__ __align__(256) __half g_Bpi[NTILES * KS_PI * 2048];

// ---------------- helpers ----------------
__device__ __forceinline__ float warp_sum(float v) {
#pragma unroll
    for (int o = 16; o > 0; o >>= 1) v += __shfl_xor_sync(0xffffffffu, v, o);
    return v;
}
__device__ __forceinline__ void cp16s(unsigned saddr, const void* g) {
    asm volatile("cp.async.cg.shared.global [%0], [%1], 16;" :: "r"(saddr), "l"(g));
}
__device__ __forceinline__ void cp_commit() {
    asm volatile("cp.async.commit_group;" ::: "memory");
}
template <int N>
__device__ __forceinline__ void cp_wait() {
    asm volatile("cp.async.wait_group %0;" :: "n"(N) : "memory");
}

// ============================================================
// Kernel 1: alpha — 8 consecutive t per warp, float4 weight LDS
// ============================================================
__global__ __launch_bounds__(256) void alpha_kernel(
    const float* __restrict__ fs,
    const float* __restrict__ conv_w,
    const float* __restrict__ ln_w,  const float* __restrict__ ln_b,
    const float* __restrict__ dense_w, const float* __restrict__ dense_b,
    const float* __restrict__ proj_w,  const float* __restrict__ proj_b,
    float* __restrict__ alpha_out)
{
    __shared__ float4 s_dw4[CC * 32];
    __shared__ float4 s_db4[32], s_pw4[32];
    __shared__ float  s_cw[CC * 3], s_lnw[CC], s_lnb[CC];

    int tid = threadIdx.x;
    for (int i = tid; i < CC * HID; i += 256) {
        int cc = i >> 7, j = i & 127;
        int q = j >> 5, l = j & 31;
        ((float*)s_dw4)[cc * 128 + l * 4 + q] = dense_w[i];
    }
    if (tid < HID) {
        int q = tid >> 5, l = tid & 31;
        ((float*)s_db4)[l * 4 + q] = dense_b[tid];
        ((float*)s_pw4)[l * 4 + q] = proj_w[tid];
    }
    if (tid < CC * 3) s_cw[tid] = conv_w[tid];
    if (tid < CC) { s_lnw[tid] = ln_w[tid]; s_lnb[tid] = ln_b[tid]; }
    __syncthreads();

    int warp = tid >> 5, lane = tid & 31;
    int g = blockIdx.x * 8 + warp;           // 6000 warp-groups
    int t0 = (g * 8) % TT;                   // TT % 8 == 0: no row straddle
    int b  = (g * 8) / TT;

    const float* base = fs + ((size_t)b * TT + t0) * CC + lane;
    float xv[10];
#pragma unroll
    for (int j = 0; j < 10; j++) {
        int t = t0 - 1 + j;
        xv[j] = (t >= 0 && t < TT) ? base[(j - 1) * CC] : 0.f;
    }

    float cw0 = s_cw[lane * 3], cw1 = s_cw[lane * 3 + 1], cw2 = s_cw[lane * 3 + 2];
    float lnw = s_lnw[lane], lnb = s_lnb[lane];

    float xn[8];
#pragma unroll
    for (int i = 0; i < 8; i++) {
        float x = fmaf(cw0, xv[i], fmaf(cw1, xv[i + 1], cw2 * xv[i + 2])) + xv[i + 1];
        float mu  = warp_sum(x) * (1.f / CC);
        float d   = x - mu;
        float var = warp_sum(d * d) * (1.f / CC);
        xn[i] = d * rsqrtf(var + 1e-5f) * lnw + lnb;
    }

    float4 db = s_db4[lane];
    float4 h[8] = {db, db, db, db, db, db, db, db};
#pragma unroll
    for (int cc = 0; cc < CC; cc++) {
        float4 w = s_dw4[cc * 32 + lane];
#pragma unroll
        for (int i = 0; i < 8; i++) {
            float v = __shfl_sync(0xffffffffu, xn[i], cc);
            h[i].x = fmaf(v, w.x, h[i].x);
            h[i].y = fmaf(v, w.y, h[i].y);
            h[i].z = fmaf(v, w.z, h[i].z);
            h[i].w = fmaf(v, w.w, h[i].w);
        }
    }

    float4 pw = s_pw4[lane];
    float ps[8];
#pragma unroll
    for (int i = 0; i < 8; i++) {
        float p = fmaxf(h[i].x, 0.f) * pw.x + fmaxf(h[i].y, 0.f) * pw.y
                + fmaxf(h[i].z, 0.f) * pw.z + fmaxf(h[i].w, 0.f) * pw.w;
        ps[i] = warp_sum(p);
    }

    if (lane < 8) {
        float psel = ps[0];
#pragma unroll
        for (int i = 1; i < 8; i++) if (lane == i) psel = ps[i];
        float a  = psel + proj_b[0];
        float sp = fmaxf(a, 0.f) + log1pf(expf(-fabsf(a)));
        alpha_out[(size_t)b * TT + t0 + lane] = sp;
    }
}

// ============================================================
// Kernel 2: fires (warp-scan, 2 barriers)
// ============================================================
__global__ __launch_bounds__(1024) void fires_kernel(
    const float* __restrict__ alpha, const int* __restrict__ tlen)
{
    __shared__ int   s_wsum[32];
    __shared__ int   s_frame[NF];
    __shared__ float s_red[32];

    int b = blockIdx.x, tid = threadIdx.x;
    int lane = tid & 31, warp = tid >> 5;
    if (tid < NF) s_frame[tid] = TT - 1;

    const float* arow = alpha + (size_t)b * TT;
    int base = tid * 3;
    int pred[3] = {0, 0, 0};
    int mycnt = 0; float onset = 0.f;
#pragma unroll
    for (int i = 0; i < 3; i++) {
        int t = base + i;
        if (t < TT) {
            float a = arow[t];
            int pr = (a > 1.0f);
            pred[i] = pr; mycnt += pr;
            onset += 1.f / (1.f + expf(-(a - 1.0f) * 10.f));
        }
    }
    int scan = mycnt;
#pragma unroll
    for (int o = 1; o < 32; o <<= 1) {
        int v = __shfl_up_sync(0xffffffffu, scan, o);
        if (lane >= o) scan += v;
    }
    if (lane == 31) s_wsum[warp] = scan;
    float os = warp_sum(onset);
    if (lane == 0) s_red[warp] = os;
    __syncthreads();
    if (warp == 0) {
        int ws = s_wsum[lane];
#pragma unroll
        for (int o = 1; o < 32; o <<= 1) {
            int v = __shfl_up_sync(0xffffffffu, ws, o);
            if (lane >= o) ws += v;
        }
        s_wsum[lane] = ws;
        float v = warp_sum(s_red[lane]);
        if (lane == 0) g_qdiff[b] = fabsf(v - (float)tlen[b]);
    }
    __syncthreads();
    int c = scan - mycnt + (warp > 0 ? s_wsum[warp - 1] : 0);
#pragma unroll
    for (int i = 0; i < 3; i++) {
        if (pred[i]) {
            c += 1;
            if (c <= NF) s_frame[c - 1] = base + i;
        }
    }
    __syncthreads();
    if (tid < NF) g_fire_w[b * NF + tid] = s_frame[tid] >> 3;
}

__global__ void qty_kernel(float* __restrict__ out) {
    int tid = threadIdx.x;
    float v = (tid < BB) ? g_qdiff[tid] : 0.f;
    v = warp_sum(v);
    if (tid == 0) out[0] = v * (1.f / BB);
}

// ============================================================
// Packing kernels (fp16 RN, bias row folded, k-step blocked)
// ============================================================
__global__ __launch_bounds__(256) void pack_b_kernel(
    const float* __restrict__ sw_w, const float* __restrict__ sw_b,
    const float* __restrict__ pi_w, const float* __restrict__ pi_b)
{
    int idx = blockIdx.x * 256 + threadIdx.x;
    const int SWTOT = NTILES * KS_SW * 2048;
    if (idx < SWTOT) {
        int nt = idx / (KS_SW * 2048);
        int rem = idx % (KS_SW * 2048);
        int j = rem / 2048, e = rem % 2048;
        int kr = e >> 7, n = e & 127;
        int k = j * 16 + kr;
        float v = (k < DSW) ? sw_w[k * DMODEL + nt * 128 + n]
                : (k == DSW ? sw_b[nt * 128 + n] : 0.f);
        g_Bsw[idx] = __float2half_rn(v);
    } else {
        int x = idx - SWTOT;
        if (x >= NTILES * KS_PI * 2048) return;
        int nt = x / (KS_PI * 2048);
        int rem = x % (KS_PI * 2048);
        int j = rem / 2048, e = rem % 2048;
        int kr = e >> 7, n = e & 127;
        int k = j * 16 + kr;
        float v = (k < 32) ? pi_w[k * DMODEL + nt * 128 + n]
                : (k == 32 ? pi_b[nt * 128 + n] : 0.f);
        g_Bpi[x] = __float2half_rn(v);
    }
}

__global__ __launch_bounds__(256) void pack_a_pitch(const float* __restrict__ pitch)
{
    int warp = threadIdx.x >> 5, lane = threadIdx.x & 31;
    int r = blockIdx.x * 8 + warp;
    float v = pitch[(size_t)r * 32 + lane];
    g_Api[((size_t)(lane >> 4) * NROWS + r) * 16 + (lane & 15)] = __float2half_rn(v);
    if (lane < 16)
        g_Api[((size_t)2 * NROWS + r) * 16 + lane] =
            __float2half_rn(lane == 0 ? 1.f : 0.f);
}

__global__ __launch_bounds__(256) void pack_a_swin(const float* __restrict__ swin)
{
    int warp = threadIdx.x >> 5, lane = threadIdx.x & 31;
    int r = blockIdx.x * 8 + warp;
    int b = r >> 12, n = (r >> 5) & 127, h = r & 31;
    int w = g_fire_w[b * NF + n];
    const float* src = swin + (size_t)((b * HH + h) * WW + w) * DSW;
#pragma unroll
    for (int j = 0; j < 6; j++) {
        int k = j * 32 + lane;
        float v = src[k];
        g_Asw[((size_t)(k >> 4) * NROWS + r) * 16 + (k & 15)] = __float2half_rn(v);
    }
    if (lane < 16)
        g_Asw[((size_t)12 * NROWS + r) * 16 + lane] =
            __float2half_rn(lane == 0 ? 1.f : 0.f);
}

// ============================================================
// fp16 wmma GEMM: 128x128 tile, k-step(16) multistage cp.async
// (R7-proven static-smem version, rolled k loop)
// ============================================================
#define ASTR 24     // halves (48B rows)
#define BSTR 136    // halves (272B rows)

template<int KSTEPS, int NSTAGE, int SLOTBASE>
__global__ __launch_bounds__(256, 2) void gemm_fp16(float* __restrict__ out)
{
    __shared__ __align__(16) __half As[NSTAGE][128 * ASTR];
    __shared__ __align__(16) __half Bs[NSTAGE][16 * BSTR];

    const __half* __restrict__ Apk = (SLOTBASE == 0) ? g_Api : g_Asw;
    const __half* __restrict__ Bpk = (SLOTBASE == 0) ? g_Bpi : g_Bsw;

    int tid = threadIdx.x;
    int m0 = blockIdx.y * 128;
    int nt = blockIdx.x;
    int n0 = nt * 128;

    unsigned sA = (unsigned)__cvta_generic_to_shared(&As[0][0]);
    unsigned sB = (unsigned)__cvta_generic_to_shared(&Bs[0][0]);
    const unsigned ASTAGE = 128 * ASTR * sizeof(__half);
    const unsigned BSTAGE = 16 * BSTR * sizeof(__half);

    int arow = tid >> 1, aseg = tid & 1;
    int brow = tid >> 4, bseg = tid & 15;

    auto load_stage = [&](int j, int st) {
        const __half* asrc = Apk + ((size_t)j * NROWS + m0) * 16;
        const __half* bsrc = Bpk + (size_t)(nt * KSTEPS + j) * 2048;
        cp16s(sA + st * ASTAGE + arow * (ASTR * 2) + aseg * 16,
              asrc + arow * 16 + aseg * 8);
        cp16s(sB + st * BSTAGE + brow * (BSTR * 2) + bseg * 16,
              bsrc + brow * 128 + bseg * 8);
    };

    int warp = tid >> 5;
    int wm = warp & 1, wn = warp >> 1;

    wmma::fragment<wmma::accumulator, 16, 16, 16, float> acc[4][2];
#pragma unroll
    for (int mi = 0; mi < 4; mi++)
#pragma unroll
        for (int ni = 0; ni < 2; ni++) wmma::fill_fragment(acc[mi][ni], 0.f);

#pragma unroll
    for (int p = 0; p < NSTAGE - 1; p++) { load_stage(p, p); cp_commit(); }

    for (int j = 0; j < KSTEPS; j++) {
        int st = j % NSTAGE;
        cp_wait<NSTAGE - 2>();
        __syncthreads();

        int jn = j + NSTAGE - 1;
        if (jn < KSTEPS) load_stage(jn, jn % NSTAGE);
        cp_commit();

        const __half* Ac = &As[0][0] + st * 128 * ASTR;
        const __half* Bc = &Bs[0][0] + st * 16 * BSTR;

        wmma::fragment<wmma::matrix_a, 16, 16, 16, __half, wmma::row_major> af[4];
        wmma::fragment<wmma::matrix_b, 16, 16, 16, __half, wmma::row_major> bf[2];
#pragma unroll
        for (int mi = 0; mi < 4; mi++)
            wmma::load_matrix_sync(af[mi], Ac + (wm * 64 + mi * 16) * ASTR, ASTR);
#pragma unroll
        for (int ni = 0; ni < 2; ni++)
            wmma::load_matrix_sync(bf[ni], Bc + wn * 32 + ni * 16, BSTR);
#pragma unroll
        for (int mi = 0; mi < 4; mi++)
#pragma unroll
            for (int ni = 0; ni < 2; ni++)
                wmma::mma_sync(acc[mi][ni], af[mi], bf[ni], acc[mi][ni]);
    }

#pragma unroll
    for (int mi = 0; mi < 4; mi++)
#pragma unroll
        for (int ni = 0; ni < 2; ni++) {
            int r0 = m0 + wm * 64 + mi * 16;
            size_t off = (size_t)(r0 >> 5) * 32768
                       + (size_t)((r0 & 31) + SLOTBASE) * 512
                       + n0 + wn * 32 + ni * 16;
            wmma::store_matrix_sync(out + off, acc[mi][ni], 512, wmma::mem_row_major);
        }
}

// ============================================================
extern "C" void kernel_launch(void* const* d_in, const int* in_sizes, int n_in,
                              void* d_out, int out_size)
{
    const float* fs      = (const float*)d_in[0];
    const float* swin    = (const float*)d_in[1];
    const float* pitch   = (const float*)d_in[2];
    const int*   tlen    = (const int*)  d_in[3];
    const float* conv_w  = (const float*)d_in[4];
    const float* ln_w    = (const float*)d_in[5];
    const float* ln_b    = (const float*)d_in[6];
    const float* dense_w = (const float*)d_in[7];
    const float* dense_b = (const float*)d_in[8];
    const float* proj_w  = (const float*)d_in[9];
    const float* proj_b  = (const float*)d_in[10];
    const float* pitch_w = (const float*)d_in[11];
    const float* pitch_b = (const float*)d_in[12];
    const float* swin_w  = (const float*)d_in[13];
    const float* swin_b  = (const float*)d_in[14];
    float* out = (float*)d_out;

    static cudaStream_t s1 = nullptr;
    static cudaEvent_t ev_root = nullptr, ev_join = nullptr, ev_end = nullptr;
    static bool init_tried = false;
    if (!init_tried) {
        init_tried = true;
        if (cudaStreamCreateWithFlags(&s1, cudaStreamNonBlocking) != cudaSuccess) s1 = nullptr;
        if (s1) {
            if (cudaEventCreateWithFlags(&ev_root, cudaEventDisableTiming) != cudaSuccess ||
                cudaEventCreateWithFlags(&ev_join, cudaEventDisableTiming) != cudaSuccess ||
                cudaEventCreateWithFlags(&ev_end,  cudaEventDisableTiming) != cudaSuccess) {
                s1 = nullptr;
            }
        }
    }

    dim3 grid(NTILES, NROWS / 128);   // (4, 512)

    if (s1) {
        cudaEventRecord(ev_root, 0);
        cudaStreamWaitEvent(s1, ev_root, 0);

        // s1: independent pitch chain
        pack_b_kernel<<<(NTILES * (KS_SW + KS_PI) * 2048 + 255) / 256, 256, 0, s1>>>(
            swin_w, swin_b, pitch_w, pitch_b);
        pack_a_pitch<<<NROWS / 8, 256, 0, s1>>>(pitch);
        gemm_fp16<KS_PI, 3, 0><<<grid, 256, 0, s1>>>(out);

        // s0: main chain
        alpha_kernel<<<750, 256>>>(fs, conv_w, ln_w, ln_b,
                                   dense_w, dense_b, proj_w, proj_b,
                                   out + ALPHA_OFF);
        fires_kernel<<<BB, 1024>>>(out + ALPHA_OFF, tlen);
        pack_a_swin<<<NROWS / 8, 256>>>(swin);

        // qty overlapped on s1 (needs only fires' g_qdiff)
        cudaEventRecord(ev_join, 0);
        cudaStreamWaitEvent(s1, ev_join, 0);
        qty_kernel<<<1, 32, 0, s1>>>(out + QTY_OFF);

        gemm_fp16<KS_SW, 4, 32><<<grid, 256>>>(out);

        cudaEventRecord(ev_end, s1);
        cudaStreamWaitEvent(0, ev_end, 0);
    } else {
        alpha_kernel<<<750, 256>>>(fs, conv_w, ln_w, ln_b,
                                   dense_w, dense_b, proj_w, proj_b,
                                   out + ALPHA_OFF);
        fires_kernel<<<BB, 1024>>>(out + ALPHA_OFF, tlen);
        qty_kernel<<<1, 32>>>(out + QTY_OFF);
        pack_b_kernel<<<(NTILES * (KS_SW + KS_PI) * 2048 + 255) / 256, 256>>>(
            swin_w, swin_b, pitch_w, pitch_b);
        pack_a_pitch<<<NROWS / 8, 256>>>(pitch);
        pack_a_swin<<<NROWS / 8, 256>>>(swin);
        gemm_fp16<KS_SW, 4, 32><<<grid, 256>>>(out);
        gemm_fp16<KS_PI, 3, 0><<<grid, 256>>>(out);
    }
}